// round 2
// baseline (speedup 1.0000x reference)
#include <cuda_runtime.h>
#include <cstdint>

#define NN 100000
#define NE 1600000
// C = 64 channels

// Scratch (device globals — no allocation allowed)
__device__ __align__(128) float g_h01[(size_t)NN * 128]; // per node: [h0(64) | h1(64)] contiguous 512B
__device__ __align__(128) float g_agg[(size_t)NN * 64];
__device__ __align__(128) float g_h[(size_t)NN * 64];    // layer-1 output
__device__ int g_deg[NN];

// ---------------- degree ----------------
__global__ void deg_zero_kernel() {
    int i = blockIdx.x * blockDim.x + threadIdx.x;
    if (i < NN) g_deg[i] = 0;
}

__global__ void deg_count_kernel(const int* __restrict__ ei) {
    int e = blockIdx.x * blockDim.x + threadIdx.x;
    if (e < NE) {
        int d = ei[NE + e];
        atomicAdd(&g_deg[d], 1);
    }
}

// ---------------- fused GEMM: h0 = x@w0, h1 = x@w1 (interleaved), zero agg ----------------
template <bool FROM_GLOBAL>
__global__ __launch_bounds__(256) void gemm2_kernel(const float* __restrict__ xin,
                                                    const float* __restrict__ w) {
    __shared__ float sw[2 * 64 * 64];   // 32 KB: w0 then w1, row-major [k][j]
    __shared__ float smx[8][64];

    const float* xp = FROM_GLOBAL ? g_h : xin;

    // stage weights
    for (int i = threadIdx.x; i < 2 * 64 * 64; i += 256) sw[i] = w[i];
    __syncthreads();

    int warp = threadIdx.x >> 5;
    int lane = threadIdx.x & 31;
    int row = blockIdx.x * 8 + warp;
    if (row >= NN) return;

    // stage x row
    float2 xv = *(const float2*)&xp[(size_t)row * 64 + lane * 2];
    smx[warp][lane * 2] = xv.x;
    smx[warp][lane * 2 + 1] = xv.y;
    __syncwarp();

    float2 a0 = make_float2(0.f, 0.f);
    float2 a1 = make_float2(0.f, 0.f);
#pragma unroll
    for (int k = 0; k < 64; k++) {
        float xk = smx[warp][k];
        float2 w0 = *(const float2*)&sw[k * 64 + lane * 2];
        float2 w1 = *(const float2*)&sw[4096 + k * 64 + lane * 2];
        a0.x = fmaf(xk, w0.x, a0.x);
        a0.y = fmaf(xk, w0.y, a0.y);
        a1.x = fmaf(xk, w1.x, a1.x);
        a1.y = fmaf(xk, w1.y, a1.y);
    }
    size_t base = (size_t)row * 128;
    *(float2*)&g_h01[base + lane * 2] = a0;
    *(float2*)&g_h01[base + 64 + lane * 2] = a1;
    *(float2*)&g_agg[(size_t)row * 64 + lane * 2] = make_float2(0.f, 0.f);
}

// ---------------- edge scatter: agg[dst] += (1-u)*h0[src] + u*h1[src] ----------------
__global__ __launch_bounds__(256) void scatter_kernel(const int* __restrict__ ei,
                                                      const float* __restrict__ u) {
    int gw = (blockIdx.x * blockDim.x + threadIdx.x) >> 5; // global warp id
    int lane = threadIdx.x & 31;
    int sub = lane >> 4;                 // half-warp handles one edge
    int e = gw * 2 + sub;
    if (e >= NE) return;
    int c = (lane & 15) * 4;             // 16 lanes x float4 = 64 cols

    int s = ei[e];
    int d = ei[NE + e];
    float ue = u[e];
    float w0 = 1.0f - ue;

    size_t sbase = (size_t)s * 128;
    float4 a = *(const float4*)&g_h01[sbase + c];
    float4 b = *(const float4*)&g_h01[sbase + 64 + c];

    float4 m;
    m.x = fmaf(w0, a.x, ue * b.x);
    m.y = fmaf(w0, a.y, ue * b.y);
    m.z = fmaf(w0, a.z, ue * b.z);
    m.w = fmaf(w0, a.w, ue * b.w);

    float* dp = &g_agg[(size_t)d * 64 + c];
    asm volatile("red.global.add.v4.f32 [%0], {%1, %2, %3, %4};"
                 :: "l"(dp), "f"(m.x), "f"(m.y), "f"(m.z), "f"(m.w)
                 : "memory");
}

// ---------------- finalize: out = agg/max(deg,1) + x@root + bias ----------------
template <bool TO_GLOBAL>
__global__ __launch_bounds__(256) void finalize_kernel(const float* __restrict__ xin,
                                                       bool from_global_x,
                                                       const float* __restrict__ root,
                                                       const float* __restrict__ bias,
                                                       float* __restrict__ out) {
    __shared__ float sw[64 * 64];  // 16 KB
    __shared__ float sb[64];
    __shared__ float smx[8][64];

    const float* xp = from_global_x ? g_h : xin;
    float* op = TO_GLOBAL ? g_h : out;

    for (int i = threadIdx.x; i < 64 * 64; i += 256) sw[i] = root[i];
    if (threadIdx.x < 64) sb[threadIdx.x] = bias[threadIdx.x];
    __syncthreads();

    int warp = threadIdx.x >> 5;
    int lane = threadIdx.x & 31;
    int row = blockIdx.x * 8 + warp;
    if (row >= NN) return;

    float2 xv = *(const float2*)&xp[(size_t)row * 64 + lane * 2];
    smx[warp][lane * 2] = xv.x;
    smx[warp][lane * 2 + 1] = xv.y;
    __syncwarp();

    float2 r = make_float2(0.f, 0.f);
#pragma unroll
    for (int k = 0; k < 64; k++) {
        float xk = smx[warp][k];
        float2 wv = *(const float2*)&sw[k * 64 + lane * 2];
        r.x = fmaf(xk, wv.x, r.x);
        r.y = fmaf(xk, wv.y, r.y);
    }

    float invd = 1.0f / fmaxf((float)g_deg[row], 1.0f);
    float2 ag = *(const float2*)&g_agg[(size_t)row * 64 + lane * 2];
    float2 o;
    o.x = fmaf(ag.x, invd, r.x + sb[lane * 2]);
    o.y = fmaf(ag.y, invd, r.y + sb[lane * 2 + 1]);
    *(float2*)&op[(size_t)row * 64 + lane * 2] = o;
}

extern "C" void kernel_launch(void* const* d_in, const int* in_sizes, int n_in,
                              void* d_out, int out_size) {
    const float* x        = (const float*)d_in[0];
    const int* ei         = (const int*)d_in[1];
    const float* eattr    = (const float*)d_in[2];
    const float* w1       = (const float*)d_in[3];
    const float* root1    = (const float*)d_in[4];
    const float* b1       = (const float*)d_in[5];
    const float* w2       = (const float*)d_in[6];
    const float* root2    = (const float*)d_in[7];
    const float* b2       = (const float*)d_in[8];
    float* out            = (float*)d_out;

    const int ROW_BLOCKS = (NN + 7) / 8;          // 12500 (8 rows/block)
    const int EDGE_BLOCKS = (NE + 15) / 16;       // 100000 (16 edges/block)

    // degree (shared by both layers)
    deg_zero_kernel<<<(NN + 255) / 256, 256>>>();
    deg_count_kernel<<<(NE + 255) / 256, 256>>>(ei);

    // layer 1
    gemm2_kernel<false><<<ROW_BLOCKS, 256>>>(x, w1);
    scatter_kernel<<<EDGE_BLOCKS, 256>>>(ei, eattr);
    finalize_kernel<true><<<ROW_BLOCKS, 256>>>(x, false, root1, b1, out);

    // layer 2 (input = g_h)
    gemm2_kernel<true><<<ROW_BLOCKS, 256>>>(nullptr, w2);
    scatter_kernel<<<EDGE_BLOCKS, 256>>>(ei, eattr);
    finalize_kernel<false><<<ROW_BLOCKS, 256>>>(nullptr, true, root2, b2, out);
}

// round 4
// speedup vs baseline: 1.6295x; 1.6295x over previous
#include <cuda_runtime.h>
#include <cstdint>

#define NN 100000
#define NE 1600000
// C = 64 channels

// Scratch (device globals — no allocation allowed)
__device__ __align__(128) float g_h01[(size_t)NN * 128]; // per node: [h0(64) | h1(64)] contiguous 512B
__device__ __align__(128) float g_agg[(size_t)NN * 64];
__device__ __align__(128) float g_r[(size_t)NN * 64];    // x@root + bias
__device__ __align__(128) float g_h[(size_t)NN * 64];    // layer-1 output
__device__ int g_deg[NN];

// ---------------- degree ----------------
__global__ void deg_zero_kernel() {
    int i = blockIdx.x * blockDim.x + threadIdx.x;
    if (i < NN) g_deg[i] = 0;
}

__global__ void deg_count_kernel(const int* __restrict__ ei) {
    int e = blockIdx.x * blockDim.x + threadIdx.x;
    if (e < NE) {
        int d = ei[NE + e];
        atomicAdd(&g_deg[d], 1);
    }
}

// ---------------- fused triple GEMM: h0=x@w0, h1=x@w1 (interleaved), r=x@root+b; zero agg ----
// Block: 256 threads = 8 warps, 32 rows/block (4 rows per warp, register-blocked).
template <bool FROM_GLOBAL>
__global__ __launch_bounds__(256) void gemm3_kernel(const float* __restrict__ xin,
                                                    const float* __restrict__ w,
                                                    const float* __restrict__ root,
                                                    const float* __restrict__ bias) {
    __shared__ float sw[3 * 4096];   // 48 KB: w0 | w1 | root, each [k][j] row-major
    __shared__ float sx[32 * 64];    // 8 KB: 32 x-rows
    __shared__ float sb[64];

    const float* xp = FROM_GLOBAL ? g_h : xin;
    const int tid = threadIdx.x;

    // stage weights (w0,w1 contiguous in w; root separate)
    for (int i = tid; i < 2 * 4096; i += 256) sw[i] = w[i];
    for (int i = tid; i < 4096; i += 256) sw[2 * 4096 + i] = root[i];
    if (tid < 64) sb[tid] = bias[tid];

    // stage 32 x-rows as float4
    const int base = blockIdx.x * 32;
    {
        const float4* xsrc = (const float4*)&xp[(size_t)base * 64];
        float4* xdst = (float4*)sx;
#pragma unroll
        for (int i = tid; i < 512; i += 256) xdst[i] = xsrc[i];
    }
    __syncthreads();

    const int warp = tid >> 5;
    const int lane = tid & 31;
    const int r0 = warp * 4;        // local row base (4 rows per warp)
    const int j = lane * 2;         // output col pair

    float2 acc[4][3];
#pragma unroll
    for (int i = 0; i < 4; i++)
#pragma unroll
        for (int m = 0; m < 3; m++) acc[i][m] = make_float2(0.f, 0.f);

#pragma unroll 4
    for (int k = 0; k < 64; k++) {
        float2 w0 = *(const float2*)&sw[k * 64 + j];
        float2 w1 = *(const float2*)&sw[4096 + k * 64 + j];
        float2 wr = *(const float2*)&sw[8192 + k * 64 + j];
        float xk0 = sx[(r0 + 0) * 64 + k];
        float xk1 = sx[(r0 + 1) * 64 + k];
        float xk2 = sx[(r0 + 2) * 64 + k];
        float xk3 = sx[(r0 + 3) * 64 + k];

        acc[0][0].x = fmaf(xk0, w0.x, acc[0][0].x); acc[0][0].y = fmaf(xk0, w0.y, acc[0][0].y);
        acc[0][1].x = fmaf(xk0, w1.x, acc[0][1].x); acc[0][1].y = fmaf(xk0, w1.y, acc[0][1].y);
        acc[0][2].x = fmaf(xk0, wr.x, acc[0][2].x); acc[0][2].y = fmaf(xk0, wr.y, acc[0][2].y);

        acc[1][0].x = fmaf(xk1, w0.x, acc[1][0].x); acc[1][0].y = fmaf(xk1, w0.y, acc[1][0].y);
        acc[1][1].x = fmaf(xk1, w1.x, acc[1][1].x); acc[1][1].y = fmaf(xk1, w1.y, acc[1][1].y);
        acc[1][2].x = fmaf(xk1, wr.x, acc[1][2].x); acc[1][2].y = fmaf(xk1, wr.y, acc[1][2].y);

        acc[2][0].x = fmaf(xk2, w0.x, acc[2][0].x); acc[2][0].y = fmaf(xk2, w0.y, acc[2][0].y);
        acc[2][1].x = fmaf(xk2, w1.x, acc[2][1].x); acc[2][1].y = fmaf(xk2, w1.y, acc[2][1].y);
        acc[2][2].x = fmaf(xk2, wr.x, acc[2][2].x); acc[2][2].y = fmaf(xk2, wr.y, acc[2][2].y);

        acc[3][0].x = fmaf(xk3, w0.x, acc[3][0].x); acc[3][0].y = fmaf(xk3, w0.y, acc[3][0].y);
        acc[3][1].x = fmaf(xk3, w1.x, acc[3][1].x); acc[3][1].y = fmaf(xk3, w1.y, acc[3][1].y);
        acc[3][2].x = fmaf(xk3, wr.x, acc[3][2].x); acc[3][2].y = fmaf(xk3, wr.y, acc[3][2].y);
    }

    float2 bv = *(const float2*)&sb[j];
#pragma unroll
    for (int i = 0; i < 4; i++) {
        size_t row = (size_t)(base + r0 + i);
        *(float2*)&g_h01[row * 128 + j]      = acc[i][0];
        *(float2*)&g_h01[row * 128 + 64 + j] = acc[i][1];
        float2 rr = make_float2(acc[i][2].x + bv.x, acc[i][2].y + bv.y);
        *(float2*)&g_r[row * 64 + j] = rr;
        *(float2*)&g_agg[row * 64 + j] = make_float2(0.f, 0.f);
    }
}

// ---------------- edge scatter: agg[dst] += (1-u)*h0[src] + u*h1[src] ----------------
// Each warp: 4 edges (2 per half-warp), gathers issued up-front for MLP.
__global__ __launch_bounds__(256) void scatter_kernel(const int* __restrict__ ei,
                                                      const float* __restrict__ u) {
    int gw = (blockIdx.x * blockDim.x + threadIdx.x) >> 5; // global warp id
    int lane = threadIdx.x & 31;
    int sub = lane >> 4;
    int c = (lane & 15) * 4;             // 16 lanes x float4 = 64 cols

    int e0 = gw * 4 + sub;               // NE divisible by 4
    int e1 = e0 + 2;

    int s0 = ei[e0], d0 = ei[NE + e0];
    int s1 = ei[e1], d1 = ei[NE + e1];
    float u0 = u[e0], u1 = u[e1];

    const float4* p0 = (const float4*)&g_h01[(size_t)s0 * 128 + c];
    const float4* p1 = (const float4*)&g_h01[(size_t)s1 * 128 + c];
    float4 a0 = p0[0];
    float4 b0 = p0[16];                  // +64 floats
    float4 a1 = p1[0];
    float4 b1 = p1[16];

    float v0 = 1.0f - u0, v1 = 1.0f - u1;
    float4 m0, m1;
    m0.x = fmaf(v0, a0.x, u0 * b0.x); m0.y = fmaf(v0, a0.y, u0 * b0.y);
    m0.z = fmaf(v0, a0.z, u0 * b0.z); m0.w = fmaf(v0, a0.w, u0 * b0.w);
    m1.x = fmaf(v1, a1.x, u1 * b1.x); m1.y = fmaf(v1, a1.y, u1 * b1.y);
    m1.z = fmaf(v1, a1.z, u1 * b1.z); m1.w = fmaf(v1, a1.w, u1 * b1.w);

    float* q0 = &g_agg[(size_t)d0 * 64 + c];
    float* q1 = &g_agg[(size_t)d1 * 64 + c];
    asm volatile("red.global.add.v4.f32 [%0], {%1, %2, %3, %4};"
                 :: "l"(q0), "f"(m0.x), "f"(m0.y), "f"(m0.z), "f"(m0.w) : "memory");
    asm volatile("red.global.add.v4.f32 [%0], {%1, %2, %3, %4};"
                 :: "l"(q1), "f"(m1.x), "f"(m1.y), "f"(m1.z), "f"(m1.w) : "memory");
}

// ---------------- finalize (elementwise): out = agg/max(deg,1) + r ----------------
template <bool TO_GLOBAL>
__global__ __launch_bounds__(256) void finalize_kernel(float* __restrict__ out) {
    int idx = blockIdx.x * blockDim.x + threadIdx.x;  // one float4 per thread
    if (idx >= NN * 16) return;
    int row = idx >> 4;
    int c = (idx & 15) * 4;

    float* op = TO_GLOBAL ? g_h : out;
    float invd = 1.0f / fmaxf((float)g_deg[row], 1.0f);
    float4 ag = *(const float4*)&g_agg[(size_t)row * 64 + c];
    float4 rr = *(const float4*)&g_r[(size_t)row * 64 + c];
    float4 o;
    o.x = fmaf(ag.x, invd, rr.x);
    o.y = fmaf(ag.y, invd, rr.y);
    o.z = fmaf(ag.z, invd, rr.z);
    o.w = fmaf(ag.w, invd, rr.w);
    *(float4*)&op[(size_t)row * 64 + c] = o;
}

extern "C" void kernel_launch(void* const* d_in, const int* in_sizes, int n_in,
                              void* d_out, int out_size) {
    const float* x        = (const float*)d_in[0];
    const int* ei         = (const int*)d_in[1];
    const float* eattr    = (const float*)d_in[2];
    const float* w1       = (const float*)d_in[3];
    const float* root1    = (const float*)d_in[4];
    const float* b1       = (const float*)d_in[5];
    const float* w2       = (const float*)d_in[6];
    const float* root2    = (const float*)d_in[7];
    const float* b2       = (const float*)d_in[8];
    float* out            = (float*)d_out;

    const int GEMM_BLOCKS = NN / 32;               // 3125 (32 rows/block)
    const int EDGE_BLOCKS = NE / 32;               // 50000 (32 edges/block: 8 warps x 4)
    const int FIN_BLOCKS  = (NN * 16 + 255) / 256; // 6250

    // degree (shared by both layers)
    deg_zero_kernel<<<(NN + 255) / 256, 256>>>();
    deg_count_kernel<<<(NE + 255) / 256, 256>>>(ei);

    // layer 1
    gemm3_kernel<false><<<GEMM_BLOCKS, 256>>>(x, w1, root1, b1);
    scatter_kernel<<<EDGE_BLOCKS, 256>>>(ei, eattr);
    finalize_kernel<true><<<FIN_BLOCKS, 256>>>(out);

    // layer 2 (input = g_h)
    gemm3_kernel<true><<<GEMM_BLOCKS, 256>>>(nullptr, w2, root2, b2);
    scatter_kernel<<<EDGE_BLOCKS, 256>>>(ei, eattr);
    finalize_kernel<false><<<FIN_BLOCKS, 256>>>(out);
}

// round 5
// speedup vs baseline: 2.0091x; 1.2329x over previous
#include <cuda_runtime.h>
#include <cstdint>

#define NN 100000
#define NE 1600000
// C = 64 channels

// Scratch (device globals — no allocation allowed)
__device__ __align__(128) float g_h01[(size_t)NN * 128]; // per node: [h0(64) | h1(64)] contiguous 512B
__device__ __align__(128) float g_r[(size_t)NN * 64];    // x@root + bias
__device__ __align__(128) float g_h[(size_t)NN * 64];    // layer-1 output
__device__ int g_deg[NN];
__device__ int g_off[NN + 1];
__device__ int g_cursor[NN];
__device__ int g_bsum[128];
__device__ unsigned long long g_csr[NE];                 // packed (u<<32 | src), dst-grouped

// ---------------- degree + cursor zero ----------------
__global__ void deg_zero_kernel() {
    int i = blockIdx.x * blockDim.x + threadIdx.x;
    if (i < NN) { g_deg[i] = 0; g_cursor[i] = 0; }
}

__global__ void deg_count_kernel(const int* __restrict__ ei) {
    int e = blockIdx.x * blockDim.x + threadIdx.x;
    if (e < NE) atomicAdd(&g_deg[ei[NE + e]], 1);
}

// ---------------- exclusive scan of degrees -> g_off ----------------
// scan1: per-block inclusive scan (1024 elems/block), writes g_off[i+1], block totals
__global__ __launch_bounds__(1024) void scan1_kernel() {
    __shared__ int s[1024];
    int t = threadIdx.x;
    int i = blockIdx.x * 1024 + t;
    int v = (i < NN) ? g_deg[i] : 0;
    s[t] = v;
    __syncthreads();
#pragma unroll
    for (int o = 1; o < 1024; o <<= 1) {
        int tv = (t >= o) ? s[t - o] : 0;
        __syncthreads();
        s[t] += tv;
        __syncthreads();
    }
    if (i < NN) g_off[i + 1] = s[t];
    if (t == 1023) g_bsum[blockIdx.x] = s[t];
    if (i == 0) g_off[0] = 0;
}

// scan2: exclusive scan of 98 block sums (single block, 128 threads)
__global__ __launch_bounds__(128) void scan2_kernel() {
    __shared__ int s[128];
    int t = threadIdx.x;
    const int NB = (NN + 1023) / 1024;   // 98
    int v = (t < NB) ? g_bsum[t] : 0;
    s[t] = v;
    __syncthreads();
#pragma unroll
    for (int o = 1; o < 128; o <<= 1) {
        int tv = (t >= o) ? s[t - o] : 0;
        __syncthreads();
        s[t] += tv;
        __syncthreads();
    }
    // exclusive
    int excl = (t == 0) ? 0 : s[t - 1];
    __syncthreads();
    g_bsum[t] = excl;
}

// scan3: add block offsets
__global__ void scan3_kernel() {
    int i = blockIdx.x * blockDim.x + threadIdx.x;
    if (i < NN) g_off[i + 1] += g_bsum[i >> 10];
}

// ---------------- CSR fill: g_csr[off[dst] + pos] = pack(u, src) ----------------
__global__ void fill_kernel(const int* __restrict__ ei, const float* __restrict__ u) {
    int e = blockIdx.x * blockDim.x + threadIdx.x;
    if (e >= NE) return;
    int s = ei[e];
    int d = ei[NE + e];
    int pos = atomicAdd(&g_cursor[d], 1);
    unsigned long long p = ((unsigned long long)__float_as_uint(u[e]) << 32) | (unsigned)s;
    g_csr[g_off[d] + pos] = p;
}

// ---------------- fused triple GEMM: h0=x@w0, h1=x@w1 (interleaved), r=x@root+b ----
// Block: 256 threads = 8 warps, 64 rows/block (8 rows per warp, register-blocked).
template <bool FROM_GLOBAL>
__global__ __launch_bounds__(256) void gemm3_kernel(const float* __restrict__ xin,
                                                    const float* __restrict__ w,
                                                    const float* __restrict__ root,
                                                    const float* __restrict__ bias) {
    __shared__ float sw[3 * 4096];   // 48 KB: w0 | w1 | root, [k][j] row-major
    __shared__ float sx[64 * 64];    // 16 KB: 64 x-rows
    __shared__ float sb[64];

    const float* xp = FROM_GLOBAL ? g_h : xin;
    const int tid = threadIdx.x;

    for (int i = tid; i < 2 * 4096; i += 256) sw[i] = w[i];
    for (int i = tid; i < 4096; i += 256) sw[2 * 4096 + i] = root[i];
    if (tid < 64) sb[tid] = bias[tid];

    const int base = blockIdx.x * 64;
    {
        const float4* xsrc = (const float4*)xp;
        float4* xdst = (float4*)sx;
#pragma unroll
        for (int i = tid; i < 1024; i += 256) {
            int row = base + (i >> 4);
            xdst[i] = (row < NN) ? xsrc[(size_t)base * 16 + i]
                                 : make_float4(0.f, 0.f, 0.f, 0.f);
        }
    }
    __syncthreads();

    const int warp = tid >> 5;
    const int lane = tid & 31;
    const int r0 = warp * 8;        // 8 rows per warp
    const int j = lane * 2;

    float2 acc[8][3];
#pragma unroll
    for (int i = 0; i < 8; i++)
#pragma unroll
        for (int m = 0; m < 3; m++) acc[i][m] = make_float2(0.f, 0.f);

#pragma unroll 2
    for (int k = 0; k < 64; k++) {
        float2 w0 = *(const float2*)&sw[k * 64 + j];
        float2 w1 = *(const float2*)&sw[4096 + k * 64 + j];
        float2 wr = *(const float2*)&sw[8192 + k * 64 + j];
#pragma unroll
        for (int i = 0; i < 8; i++) {
            float xk = sx[(r0 + i) * 64 + k];
            acc[i][0].x = fmaf(xk, w0.x, acc[i][0].x);
            acc[i][0].y = fmaf(xk, w0.y, acc[i][0].y);
            acc[i][1].x = fmaf(xk, w1.x, acc[i][1].x);
            acc[i][1].y = fmaf(xk, w1.y, acc[i][1].y);
            acc[i][2].x = fmaf(xk, wr.x, acc[i][2].x);
            acc[i][2].y = fmaf(xk, wr.y, acc[i][2].y);
        }
    }

    float2 bv = *(const float2*)&sb[j];
#pragma unroll
    for (int i = 0; i < 8; i++) {
        int row = base + r0 + i;
        if (row < NN) {
            *(float2*)&g_h01[(size_t)row * 128 + j]      = acc[i][0];
            *(float2*)&g_h01[(size_t)row * 128 + 64 + j] = acc[i][1];
            float2 rr = make_float2(acc[i][2].x + bv.x, acc[i][2].y + bv.y);
            *(float2*)&g_r[(size_t)row * 64 + j] = rr;
        }
    }
}

// ---------------- pull aggregation + fused finalize ----------------
// One half-warp (16 lanes, float4 each) per node: acc = sum over csr edges,
// out = acc/max(deg,1) + r.  No atomics.
template <bool TO_GLOBAL>
__global__ __launch_bounds__(256) void pull_kernel(float* __restrict__ out) {
    int node = blockIdx.x * 16 + (threadIdx.x >> 4);   // NN divisible by 16
    int c = (threadIdx.x & 15) * 4;

    int beg = g_off[node];
    int end = g_off[node + 1];

    float4 acc = make_float4(0.f, 0.f, 0.f, 0.f);
    int i = beg;

    // 4-way unrolled: issue all csr loads, then all gathers, then math
    for (; i + 3 < end; i += 4) {
        unsigned long long p0 = g_csr[i];
        unsigned long long p1 = g_csr[i + 1];
        unsigned long long p2 = g_csr[i + 2];
        unsigned long long p3 = g_csr[i + 3];
        const float4* q0 = (const float4*)&g_h01[(size_t)(unsigned)(p0 & 0xffffffffu) * 128 + c];
        const float4* q1 = (const float4*)&g_h01[(size_t)(unsigned)(p1 & 0xffffffffu) * 128 + c];
        const float4* q2 = (const float4*)&g_h01[(size_t)(unsigned)(p2 & 0xffffffffu) * 128 + c];
        const float4* q3 = (const float4*)&g_h01[(size_t)(unsigned)(p3 & 0xffffffffu) * 128 + c];
        float4 a0 = q0[0], b0 = q0[16];
        float4 a1 = q1[0], b1 = q1[16];
        float4 a2 = q2[0], b2 = q2[16];
        float4 a3 = q3[0], b3 = q3[16];
        float u0 = __uint_as_float((unsigned)(p0 >> 32));
        float u1 = __uint_as_float((unsigned)(p1 >> 32));
        float u2 = __uint_as_float((unsigned)(p2 >> 32));
        float u3 = __uint_as_float((unsigned)(p3 >> 32));
        float v0 = 1.f - u0, v1 = 1.f - u1, v2 = 1.f - u2, v3 = 1.f - u3;
        acc.x += fmaf(v0, a0.x, u0 * b0.x) + fmaf(v1, a1.x, u1 * b1.x)
               + fmaf(v2, a2.x, u2 * b2.x) + fmaf(v3, a3.x, u3 * b3.x);
        acc.y += fmaf(v0, a0.y, u0 * b0.y) + fmaf(v1, a1.y, u1 * b1.y)
               + fmaf(v2, a2.y, u2 * b2.y) + fmaf(v3, a3.y, u3 * b3.y);
        acc.z += fmaf(v0, a0.z, u0 * b0.z) + fmaf(v1, a1.z, u1 * b1.z)
               + fmaf(v2, a2.z, u2 * b2.z) + fmaf(v3, a3.z, u3 * b3.z);
        acc.w += fmaf(v0, a0.w, u0 * b0.w) + fmaf(v1, a1.w, u1 * b1.w)
               + fmaf(v2, a2.w, u2 * b2.w) + fmaf(v3, a3.w, u3 * b3.w);
    }
    for (; i < end; i++) {
        unsigned long long p = g_csr[i];
        const float4* q = (const float4*)&g_h01[(size_t)(unsigned)(p & 0xffffffffu) * 128 + c];
        float4 a = q[0], b = q[16];
        float u = __uint_as_float((unsigned)(p >> 32));
        float v = 1.f - u;
        acc.x += fmaf(v, a.x, u * b.x);
        acc.y += fmaf(v, a.y, u * b.y);
        acc.z += fmaf(v, a.z, u * b.z);
        acc.w += fmaf(v, a.w, u * b.w);
    }

    float invd = 1.0f / fmaxf((float)(end - beg), 1.0f);
    float4 rr = *(const float4*)&g_r[(size_t)node * 64 + c];
    float4 o;
    o.x = fmaf(acc.x, invd, rr.x);
    o.y = fmaf(acc.y, invd, rr.y);
    o.z = fmaf(acc.z, invd, rr.z);
    o.w = fmaf(acc.w, invd, rr.w);
    float* op = TO_GLOBAL ? g_h : out;
    *(float4*)&op[(size_t)node * 64 + c] = o;
}

extern "C" void kernel_launch(void* const* d_in, const int* in_sizes, int n_in,
                              void* d_out, int out_size) {
    const float* x        = (const float*)d_in[0];
    const int* ei         = (const int*)d_in[1];
    const float* eattr    = (const float*)d_in[2];
    const float* w1       = (const float*)d_in[3];
    const float* root1    = (const float*)d_in[4];
    const float* b1       = (const float*)d_in[5];
    const float* w2       = (const float*)d_in[6];
    const float* root2    = (const float*)d_in[7];
    const float* b2       = (const float*)d_in[8];
    float* out            = (float*)d_out;

    const int GEMM_BLOCKS = (NN + 63) / 64;        // 1563
    const int PULL_BLOCKS = NN / 16;               // 6250
    const int SCAN_BLOCKS = (NN + 1023) / 1024;    // 98

    // CSR build (edges shared by both layers)
    deg_zero_kernel<<<(NN + 255) / 256, 256>>>();
    deg_count_kernel<<<(NE + 255) / 256, 256>>>(ei);
    scan1_kernel<<<SCAN_BLOCKS, 1024>>>();
    scan2_kernel<<<1, 128>>>();
    scan3_kernel<<<(NN + 255) / 256, 256>>>();
    fill_kernel<<<(NE + 255) / 256, 256>>>(ei, eattr);

    // layer 1
    gemm3_kernel<false><<<GEMM_BLOCKS, 256>>>(x, w1, root1, b1);
    pull_kernel<true><<<PULL_BLOCKS, 256>>>(out);

    // layer 2 (input = g_h)
    gemm3_kernel<true><<<GEMM_BLOCKS, 256>>>(nullptr, w2, root2, b2);
    pull_kernel<false><<<PULL_BLOCKS, 256>>>(out);
}

// round 6
// speedup vs baseline: 2.3965x; 1.1928x over previous
#include <cuda_runtime.h>
#include <cuda_fp16.h>
#include <cstdint>

#define NN 100000
#define NE 1600000
// C = 64 channels

// Scratch (device globals — no allocation allowed)
__device__ __align__(128) unsigned int g_h01h[(size_t)NN * 64]; // per node: 64 x half2(h0[c],h1[c]) = 256B
__device__ __align__(128) float g_r[(size_t)NN * 64];           // x@root + bias
__device__ __align__(128) float g_h[(size_t)NN * 64];           // layer-1 output
__device__ int g_deg[NN];
__device__ int g_off[NN + 1];
__device__ int g_cursor[NN];
__device__ int g_bsum[128];
__device__ unsigned long long g_csr[NE];                 // packed (u<<32 | src), dst-grouped

// ---------------- degree + cursor zero ----------------
__global__ void deg_zero_kernel() {
    int i = blockIdx.x * blockDim.x + threadIdx.x;
    if (i < NN) { g_deg[i] = 0; g_cursor[i] = 0; }
}

__global__ void deg_count_kernel(const int* __restrict__ ei) {
    int e = blockIdx.x * blockDim.x + threadIdx.x;
    if (e < NE) atomicAdd(&g_deg[ei[NE + e]], 1);
}

// ---------------- exclusive scan of degrees -> g_off ----------------
// scan1: per-block inclusive scan (1024 elems/block), writes g_off[i+1], block totals
__global__ __launch_bounds__(1024) void scan1_kernel() {
    __shared__ int s[1024];
    int t = threadIdx.x;
    int i = blockIdx.x * 1024 + t;
    int v = (i < NN) ? g_deg[i] : 0;
    s[t] = v;
    __syncthreads();
#pragma unroll
    for (int o = 1; o < 1024; o <<= 1) {
        int tv = (t >= o) ? s[t - o] : 0;
        __syncthreads();
        s[t] += tv;
        __syncthreads();
    }
    if (i < NN) g_off[i + 1] = s[t];
    if (t == 1023) g_bsum[blockIdx.x] = s[t];
    if (i == 0) g_off[0] = 0;
}

// scan23: each block redundantly scans the 98 block sums in smem, then adds
// the exclusive block offset to its slice of g_off.
__global__ __launch_bounds__(256) void scan23_kernel() {
    __shared__ int s[128];
    int t = threadIdx.x;
    const int NB = (NN + 1023) / 1024;   // 98
    if (t < 128) s[t] = (t < NB) ? g_bsum[t] : 0;
    __syncthreads();
#pragma unroll
    for (int o = 1; o < 128; o <<= 1) {
        int tv = (t >= o && t < 128) ? s[t - o] : 0;
        __syncthreads();
        if (t < 128) s[t] += tv;
        __syncthreads();
    }
    int i = blockIdx.x * 256 + t;
    if (i < NN) {
        int b = i >> 10;
        int add = (b == 0) ? 0 : s[b - 1];
        g_off[i + 1] += add;
    }
}

// ---------------- CSR fill: g_csr[off[dst] + pos] = pack(u, src) ----------------
__global__ void fill_kernel(const int* __restrict__ ei, const float* __restrict__ u) {
    int e = blockIdx.x * blockDim.x + threadIdx.x;
    if (e >= NE) return;
    int s = ei[e];
    int d = ei[NE + e];
    int pos = atomicAdd(&g_cursor[d], 1);
    unsigned long long p = ((unsigned long long)__float_as_uint(u[e]) << 32) | (unsigned)s;
    g_csr[g_off[d] + pos] = p;
}

// ---------------- fused triple GEMM via packed f32x2 FMA ----------------
// h0=x@w0, h1=x@w1 -> fp16 interleaved g_h01h; r=x@root+b -> g_r (fp32).
// Block: 256 threads = 8 warps, 64 rows/block (8 rows/warp register-blocked).
template <bool FROM_GLOBAL>
__global__ __launch_bounds__(256) void gemm3_kernel(const float* __restrict__ xin,
                                                    const float* __restrict__ w,
                                                    const float* __restrict__ root,
                                                    const float* __restrict__ bias) {
    __shared__ float sw[3 * 4096];   // 48 KB: w0 | w1 | root, [k][j] row-major
    __shared__ float sx[64 * 64];    // 16 KB: 64 x-rows
    __shared__ float sb[64];

    const float* xp = FROM_GLOBAL ? g_h : xin;
    const int tid = threadIdx.x;

    for (int i = tid; i < 2 * 4096; i += 256) sw[i] = w[i];
    for (int i = tid; i < 4096; i += 256) sw[2 * 4096 + i] = root[i];
    if (tid < 64) sb[tid] = bias[tid];

    const int base = blockIdx.x * 64;
    {
        const float4* xsrc = (const float4*)xp;
        float4* xdst = (float4*)sx;
#pragma unroll
        for (int i = tid; i < 1024; i += 256) {
            int row = base + (i >> 4);
            xdst[i] = (row < NN) ? xsrc[(size_t)base * 16 + i]
                                 : make_float4(0.f, 0.f, 0.f, 0.f);
        }
    }
    __syncthreads();

    const int warp = tid >> 5;
    const int lane = tid & 31;
    const int r0 = warp * 8;        // 8 rows per warp
    const int j = lane * 2;

    unsigned long long acc[8][3];
#pragma unroll
    for (int i = 0; i < 8; i++)
#pragma unroll
        for (int m = 0; m < 3; m++) acc[i][m] = 0ull;  // bits of (0.f, 0.f)

    for (int kk = 0; kk < 64; kk += 4) {
        float4 xv[8];
#pragma unroll
        for (int i = 0; i < 8; i++)
            xv[i] = *(const float4*)&sx[(r0 + i) * 64 + kk];  // warp-broadcast LDS

#pragma unroll
        for (int t = 0; t < 4; t++) {
            int k = kk + t;
            unsigned long long w0 = *(const unsigned long long*)&sw[k * 64 + j];
            unsigned long long w1 = *(const unsigned long long*)&sw[4096 + k * 64 + j];
            unsigned long long wr = *(const unsigned long long*)&sw[8192 + k * 64 + j];
#pragma unroll
            for (int i = 0; i < 8; i++) {
                float xk = (t == 0) ? xv[i].x : (t == 1) ? xv[i].y : (t == 2) ? xv[i].z : xv[i].w;
                unsigned long long xx;
                asm("mov.b64 %0, {%1, %1};" : "=l"(xx) : "f"(xk));
                asm("fma.rn.f32x2 %0, %1, %2, %0;" : "+l"(acc[i][0]) : "l"(xx), "l"(w0));
                asm("fma.rn.f32x2 %0, %1, %2, %0;" : "+l"(acc[i][1]) : "l"(xx), "l"(w1));
                asm("fma.rn.f32x2 %0, %1, %2, %0;" : "+l"(acc[i][2]) : "l"(xx), "l"(wr));
            }
        }
    }

    float2 bv = *(const float2*)&sb[j];
#pragma unroll
    for (int i = 0; i < 8; i++) {
        int row = base + r0 + i;
        if (row < NN) {
            float a0x, a0y, a1x, a1y, arx, ary;
            asm("mov.b64 {%0, %1}, %2;" : "=f"(a0x), "=f"(a0y) : "l"(acc[i][0]));
            asm("mov.b64 {%0, %1}, %2;" : "=f"(a1x), "=f"(a1y) : "l"(acc[i][1]));
            asm("mov.b64 {%0, %1}, %2;" : "=f"(arx), "=f"(ary) : "l"(acc[i][2]));
            // interleave: half2(h0[c], h1[c]) per channel
            __half2 p0 = __floats2half2_rn(a0x, a1x);
            __half2 p1 = __floats2half2_rn(a0y, a1y);
            uint2 pk;
            pk.x = *(unsigned int*)&p0;
            pk.y = *(unsigned int*)&p1;
            *(uint2*)&g_h01h[(size_t)row * 64 + j] = pk;
            float2 rr = make_float2(arx + bv.x, ary + bv.y);
            *(float2*)&g_r[(size_t)row * 64 + j] = rr;
        }
    }
}

// ---------------- pull aggregation + fused finalize ----------------
// One half-warp (16 lanes, 4 channels/lane = one uint4 gather) per node.
// acc = sum over csr edges of (1-u)*h0 + u*h1; out = acc/max(deg,1) + r.
template <bool TO_GLOBAL>
__global__ __launch_bounds__(256) void pull_kernel(float* __restrict__ out) {
    int node = blockIdx.x * 16 + (threadIdx.x >> 4);   // NN divisible by 16
    int c4 = (threadIdx.x & 15) * 4;                   // first of 4 channels

    int beg = g_off[node];
    int end = g_off[node + 1];

    float4 acc = make_float4(0.f, 0.f, 0.f, 0.f);
    int i = beg;

    for (; i + 3 < end; i += 4) {
        unsigned long long p0 = g_csr[i];
        unsigned long long p1 = g_csr[i + 1];
        unsigned long long p2 = g_csr[i + 2];
        unsigned long long p3 = g_csr[i + 3];
        uint4 ga = *(const uint4*)&g_h01h[(size_t)(unsigned)(p0 & 0xffffffffu) * 64 + c4];
        uint4 gb = *(const uint4*)&g_h01h[(size_t)(unsigned)(p1 & 0xffffffffu) * 64 + c4];
        uint4 gc = *(const uint4*)&g_h01h[(size_t)(unsigned)(p2 & 0xffffffffu) * 64 + c4];
        uint4 gd = *(const uint4*)&g_h01h[(size_t)(unsigned)(p3 & 0xffffffffu) * 64 + c4];
        float u0 = __uint_as_float((unsigned)(p0 >> 32));
        float u1 = __uint_as_float((unsigned)(p1 >> 32));
        float u2 = __uint_as_float((unsigned)(p2 >> 32));
        float u3 = __uint_as_float((unsigned)(p3 >> 32));
        float v0 = 1.f - u0, v1 = 1.f - u1, v2 = 1.f - u2, v3 = 1.f - u3;

        float2 f;
        f = __half22float2(*(__half2*)&ga.x); acc.x += fmaf(v0, f.x, u0 * f.y);
        f = __half22float2(*(__half2*)&ga.y); acc.y += fmaf(v0, f.x, u0 * f.y);
        f = __half22float2(*(__half2*)&ga.z); acc.z += fmaf(v0, f.x, u0 * f.y);
        f = __half22float2(*(__half2*)&ga.w); acc.w += fmaf(v0, f.x, u0 * f.y);
        f = __half22float2(*(__half2*)&gb.x); acc.x += fmaf(v1, f.x, u1 * f.y);
        f = __half22float2(*(__half2*)&gb.y); acc.y += fmaf(v1, f.x, u1 * f.y);
        f = __half22float2(*(__half2*)&gb.z); acc.z += fmaf(v1, f.x, u1 * f.y);
        f = __half22float2(*(__half2*)&gb.w); acc.w += fmaf(v1, f.x, u1 * f.y);
        f = __half22float2(*(__half2*)&gc.x); acc.x += fmaf(v2, f.x, u2 * f.y);
        f = __half22float2(*(__half2*)&gc.y); acc.y += fmaf(v2, f.x, u2 * f.y);
        f = __half22float2(*(__half2*)&gc.z); acc.z += fmaf(v2, f.x, u2 * f.y);
        f = __half22float2(*(__half2*)&gc.w); acc.w += fmaf(v2, f.x, u2 * f.y);
        f = __half22float2(*(__half2*)&gd.x); acc.x += fmaf(v3, f.x, u3 * f.y);
        f = __half22float2(*(__half2*)&gd.y); acc.y += fmaf(v3, f.x, u3 * f.y);
        f = __half22float2(*(__half2*)&gd.z); acc.z += fmaf(v3, f.x, u3 * f.y);
        f = __half22float2(*(__half2*)&gd.w); acc.w += fmaf(v3, f.x, u3 * f.y);
    }
    for (; i < end; i++) {
        unsigned long long p = g_csr[i];
        uint4 ga = *(const uint4*)&g_h01h[(size_t)(unsigned)(p & 0xffffffffu) * 64 + c4];
        float u = __uint_as_float((unsigned)(p >> 32));
        float v = 1.f - u;
        float2 f;
        f = __half22float2(*(__half2*)&ga.x); acc.x += fmaf(v, f.x, u * f.y);
        f = __half22float2(*(__half2*)&ga.y); acc.y += fmaf(v, f.x, u * f.y);
        f = __half22float2(*(__half2*)&ga.z); acc.z += fmaf(v, f.x, u * f.y);
        f = __half22float2(*(__half2*)&ga.w); acc.w += fmaf(v, f.x, u * f.y);
    }

    float invd = 1.0f / fmaxf((float)(end - beg), 1.0f);
    float4 rr = *(const float4*)&g_r[(size_t)node * 64 + c4];
    float4 o;
    o.x = fmaf(acc.x, invd, rr.x);
    o.y = fmaf(acc.y, invd, rr.y);
    o.z = fmaf(acc.z, invd, rr.z);
    o.w = fmaf(acc.w, invd, rr.w);
    float* op = TO_GLOBAL ? g_h : out;
    *(float4*)&op[(size_t)node * 64 + c4] = o;
}

extern "C" void kernel_launch(void* const* d_in, const int* in_sizes, int n_in,
                              void* d_out, int out_size) {
    const float* x        = (const float*)d_in[0];
    const int* ei         = (const int*)d_in[1];
    const float* eattr    = (const float*)d_in[2];
    const float* w1       = (const float*)d_in[3];
    const float* root1    = (const float*)d_in[4];
    const float* b1       = (const float*)d_in[5];
    const float* w2       = (const float*)d_in[6];
    const float* root2    = (const float*)d_in[7];
    const float* b2       = (const float*)d_in[8];
    float* out            = (float*)d_out;

    const int GEMM_BLOCKS = (NN + 63) / 64;        // 1563
    const int PULL_BLOCKS = NN / 16;               // 6250
    const int SCAN_BLOCKS = (NN + 1023) / 1024;    // 98

    // CSR build (edges shared by both layers)
    deg_zero_kernel<<<(NN + 255) / 256, 256>>>();
    deg_count_kernel<<<(NE + 255) / 256, 256>>>(ei);
    scan1_kernel<<<SCAN_BLOCKS, 1024>>>();
    scan23_kernel<<<(NN + 255) / 256, 256>>>();
    fill_kernel<<<(NE + 255) / 256, 256>>>(ei, eattr);

    // layer 1
    gemm3_kernel<false><<<GEMM_BLOCKS, 256>>>(x, w1, root1, b1);
    pull_kernel<true><<<PULL_BLOCKS, 256>>>(out);

    // layer 2 (input = g_h)
    gemm3_kernel<true><<<GEMM_BLOCKS, 256>>>(nullptr, w2, root2, b2);
    pull_kernel<false><<<PULL_BLOCKS, 256>>>(out);
}

// round 8
// speedup vs baseline: 2.6260x; 1.0957x over previous
#include <cuda_runtime.h>
#include <cuda_fp16.h>
#include <cstdint>

#define NN 100000
#define NE 1600000
// C = 64 channels

// Scratch (device globals — no allocation allowed)
__device__ __align__(128) unsigned int g_h01h[(size_t)NN * 64]; // per node: 64 x half2(h0[c],h1[c]) = 256B
__device__ __align__(128) float g_r[(size_t)NN * 64];           // x@root + bias
__device__ __align__(128) float g_h[(size_t)NN * 64];           // layer-1 output
__device__ int g_deg[NN];
__device__ int g_off[NN + 1];
__device__ int g_cursor[NN];
__device__ int g_bsum[128];
__device__ unsigned long long g_csr[NE];                 // packed (u<<32 | src), dst-grouped

// ---------------- degree + cursor zero ----------------
__global__ void deg_zero_kernel() {
    int i = blockIdx.x * blockDim.x + threadIdx.x;
    if (i < NN) { g_deg[i] = 0; g_cursor[i] = 0; }
}

__global__ void deg_count_kernel(const int* __restrict__ ei) {
    int e = blockIdx.x * blockDim.x + threadIdx.x;
    if (e < NE) atomicAdd(&g_deg[ei[NE + e]], 1);
}

// ---------------- exclusive scan of degrees -> g_off ----------------
__global__ __launch_bounds__(1024) void scan1_kernel() {
    __shared__ int s[1024];
    int t = threadIdx.x;
    int i = blockIdx.x * 1024 + t;
    int v = (i < NN) ? g_deg[i] : 0;
    s[t] = v;
    __syncthreads();
#pragma unroll
    for (int o = 1; o < 1024; o <<= 1) {
        int tv = (t >= o) ? s[t - o] : 0;
        __syncthreads();
        s[t] += tv;
        __syncthreads();
    }
    if (i < NN) g_off[i + 1] = s[t];
    if (t == 1023) g_bsum[blockIdx.x] = s[t];
    if (i == 0) g_off[0] = 0;
}

__global__ __launch_bounds__(256) void scan23_kernel() {
    __shared__ int s[128];
    int t = threadIdx.x;
    const int NB = (NN + 1023) / 1024;   // 98
    if (t < 128) s[t] = (t < NB) ? g_bsum[t] : 0;
    __syncthreads();
#pragma unroll
    for (int o = 1; o < 128; o <<= 1) {
        int tv = (t >= o && t < 128) ? s[t - o] : 0;
        __syncthreads();
        if (t < 128) s[t] += tv;
        __syncthreads();
    }
    int i = blockIdx.x * 256 + t;
    if (i < NN) {
        int b = i >> 10;
        int add = (b == 0) ? 0 : s[b - 1];
        g_off[i + 1] += add;
    }
}

// ---------------- CSR fill: g_csr[off[dst] + pos] = pack(u, src) ----------------
__global__ void fill_kernel(const int* __restrict__ ei, const float* __restrict__ u) {
    int e = blockIdx.x * blockDim.x + threadIdx.x;
    if (e >= NE) return;
    int s = ei[e];
    int d = ei[NE + e];
    int pos = atomicAdd(&g_cursor[d], 1);
    unsigned long long p = ((unsigned long long)__float_as_uint(u[e]) << 32) | (unsigned)s;
    g_csr[g_off[d] + pos] = p;
}

// ---------------- tf32 tensor-core triple GEMM ----------------
// Out[row, 0:192] = x[row, 0:64] @ [w0 | w1 | root].
// Block: 256 threads = 8 warps; 128 rows/block; warp tile = 64 rows x 48 cols,
// where a warp's 48 cols are the SAME 16 channels in all three segments
// (h0, h1, root) so each thread can write interleaved half2(h0[c],h1[c]).
__device__ __forceinline__ float to_tf32(float v) {
    unsigned int r;
    asm("cvt.rna.tf32.f32 %0, %1;" : "=r"(r) : "f"(v));
    return __uint_as_float(r);
}

__device__ __forceinline__ void mma_tf32(float* d, const float* a, const float* b) {
    asm("mma.sync.aligned.m16n8k8.row.col.f32.tf32.tf32.f32 "
        "{%0,%1,%2,%3},{%4,%5,%6,%7},{%8,%9},{%0,%1,%2,%3};"
        : "+f"(d[0]), "+f"(d[1]), "+f"(d[2]), "+f"(d[3])
        : "r"(__float_as_uint(a[0])), "r"(__float_as_uint(a[1])),
          "r"(__float_as_uint(a[2])), "r"(__float_as_uint(a[3])),
          "r"(__float_as_uint(b[0])), "r"(__float_as_uint(b[1])));
}

template <bool FROM_GLOBAL>
__global__ __launch_bounds__(256) void gemm3_tc_kernel(const float* __restrict__ xin,
                                                       const float* __restrict__ w,
                                                       const float* __restrict__ root,
                                                       const float* __restrict__ bias) {
    __shared__ float sw[64][200];   // [k][n 0:192], pad 200: B-frag banks = 8t+g (unique)
    __shared__ float sx[128][72];   // [row][k],     pad 72:  A-frag banks = 8g+t (unique)
    __shared__ float sb[64];

    const float* xp = FROM_GLOBAL ? g_h : xin;
    const int tid = threadIdx.x;
    const int base = blockIdx.x * 128;

    // stage weights (tf32-rounded): sw[k][n] = w0, sw[k][64+n] = w1, sw[k][128+n] = root
    for (int i = tid; i < 4096; i += 256) {
        int k = i >> 6, n = i & 63;
        sw[k][n]       = to_tf32(w[i]);
        sw[k][64 + n]  = to_tf32(w[4096 + i]);
        sw[k][128 + n] = to_tf32(root[i]);
    }
    if (tid < 64) sb[tid] = bias[tid];

    // stage x rows (tf32-rounded), zero-pad past NN
    for (int i = tid; i < 2048; i += 256) {     // i over float4s
        int row = i >> 4;
        int c = (i & 15) * 4;
        float4 v = (base + row < NN)
                     ? ((const float4*)xp)[(size_t)(base + row) * 16 + (i & 15)]
                     : make_float4(0.f, 0.f, 0.f, 0.f);
        sx[row][c]     = to_tf32(v.x);
        sx[row][c + 1] = to_tf32(v.y);
        sx[row][c + 2] = to_tf32(v.z);
        sx[row][c + 3] = to_tf32(v.w);
    }
    __syncthreads();

    const int warp = tid >> 5;
    const int lane = tid & 31;
    const int g = lane >> 2;       // group id (0..7)
    const int t = lane & 3;        // thread-in-group (0..3)
    const int mg = warp >> 2;      // row group: rows [mg*64, mg*64+64)
    const int ng = warp & 3;       // channel group: channels [ng*16, ng*16+16)

    float acc[4][6][4];            // [m16-tile][n8-tile][reg] = 96 regs
#pragma unroll
    for (int mt = 0; mt < 4; mt++)
#pragma unroll
        for (int nt = 0; nt < 6; nt++)
#pragma unroll
            for (int q = 0; q < 4; q++) acc[mt][nt][q] = 0.f;

#pragma unroll
    for (int ks = 0; ks < 8; ks++) {
        const int k0 = ks * 8;
        float a[4][4];
#pragma unroll
        for (int mt = 0; mt < 4; mt++) {
            int r = mg * 64 + mt * 16 + g;
            a[mt][0] = sx[r][k0 + t];
            a[mt][1] = sx[r + 8][k0 + t];
            a[mt][2] = sx[r][k0 + t + 4];
            a[mt][3] = sx[r + 8][k0 + t + 4];
        }
        float b[6][2];
#pragma unroll
        for (int nt = 0; nt < 6; nt++) {
            // nt 0,1 -> h0; 2,3 -> h1; 4,5 -> root; within segment: cols ng*16 + (nt&1)*8 + g
            int n = (nt >> 1) * 64 + ng * 16 + (nt & 1) * 8 + g;
            b[nt][0] = sw[k0 + t][n];
            b[nt][1] = sw[k0 + t + 4][n];
        }
#pragma unroll
        for (int mt = 0; mt < 4; mt++)
#pragma unroll
            for (int nt = 0; nt < 6; nt++) mma_tf32(acc[mt][nt], a[mt], b[nt]);
    }

    // epilogue: per (mt, nt2) thread owns channels c, c+1 for rows r0 and r0+8,
    // with matching h0/h1/root values in registers.
#pragma unroll
    for (int mt = 0; mt < 4; mt++) {
#pragma unroll
        for (int nt2 = 0; nt2 < 2; nt2++) {
            const float* h0 = acc[mt][nt2];
            const float* h1 = acc[mt][2 + nt2];
            const float* rt = acc[mt][4 + nt2];
            int c = ng * 16 + nt2 * 8 + 2 * t;
            int r0 = base + mg * 64 + mt * 16 + g;
            int r1 = r0 + 8;
            float b0v = sb[c], b1v = sb[c + 1];
            if (r0 < NN) {
                __half2 pA = __floats2half2_rn(h0[0], h1[0]);
                __half2 pB = __floats2half2_rn(h0[1], h1[1]);
                uint2 pk = make_uint2(*(unsigned int*)&pA, *(unsigned int*)&pB);
                *(uint2*)&g_h01h[(size_t)r0 * 64 + c] = pk;
                *(float2*)&g_r[(size_t)r0 * 64 + c] = make_float2(rt[0] + b0v, rt[1] + b1v);
            }
            if (r1 < NN) {
                __half2 pA = __floats2half2_rn(h0[2], h1[2]);
                __half2 pB = __floats2half2_rn(h0[3], h1[3]);
                uint2 pk = make_uint2(*(unsigned int*)&pA, *(unsigned int*)&pB);
                *(uint2*)&g_h01h[(size_t)r1 * 64 + c] = pk;
                *(float2*)&g_r[(size_t)r1 * 64 + c] = make_float2(rt[2] + b0v, rt[3] + b1v);
            }
        }
    }
}

// ---------------- pull aggregation + fused finalize ----------------
template <bool TO_GLOBAL>
__global__ __launch_bounds__(256) void pull_kernel(float* __restrict__ out) {
    int node = blockIdx.x * 16 + (threadIdx.x >> 4);   // NN divisible by 16
    int c4 = (threadIdx.x & 15) * 4;                   // first of 4 channels

    int beg = g_off[node];
    int end = g_off[node + 1];

    float4 acc = make_float4(0.f, 0.f, 0.f, 0.f);
    int i = beg;

    for (; i + 3 < end; i += 4) {
        unsigned long long p0 = g_csr[i];
        unsigned long long p1 = g_csr[i + 1];
        unsigned long long p2 = g_csr[i + 2];
        unsigned long long p3 = g_csr[i + 3];
        uint4 ga = *(const uint4*)&g_h01h[(size_t)(unsigned)(p0 & 0xffffffffu) * 64 + c4];
        uint4 gb = *(const uint4*)&g_h01h[(size_t)(unsigned)(p1 & 0xffffffffu) * 64 + c4];
        uint4 gc = *(const uint4*)&g_h01h[(size_t)(unsigned)(p2 & 0xffffffffu) * 64 + c4];
        uint4 gd = *(const uint4*)&g_h01h[(size_t)(unsigned)(p3 & 0xffffffffu) * 64 + c4];
        float u0 = __uint_as_float((unsigned)(p0 >> 32));
        float u1 = __uint_as_float((unsigned)(p1 >> 32));
        float u2 = __uint_as_float((unsigned)(p2 >> 32));
        float u3 = __uint_as_float((unsigned)(p3 >> 32));
        float v0 = 1.f - u0, v1 = 1.f - u1, v2 = 1.f - u2, v3 = 1.f - u3;

        float2 f;
        f = __half22float2(*(__half2*)&ga.x); acc.x += fmaf(v0, f.x, u0 * f.y);
        f = __half22float2(*(__half2*)&ga.y); acc.y += fmaf(v0, f.x, u0 * f.y);
        f = __half22float2(*(__half2*)&ga.z); acc.z += fmaf(v0, f.x, u0 * f.y);
        f = __half22float2(*(__half2*)&ga.w); acc.w += fmaf(v0, f.x, u0 * f.y);
        f = __half22float2(*(__half2*)&gb.x); acc.x += fmaf(v1, f.x, u1 * f.y);
        f = __half22float2(*(__half2*)&gb.y); acc.y += fmaf(v1, f.x, u1 * f.y);
        f = __half22float2(*(__half2*)&gb.z); acc.z += fmaf(v1, f.x, u1 * f.y);
        f = __half22float2(*(__half2*)&gb.w); acc.w += fmaf(v1, f.x, u1 * f.y);
        f = __half22float2(*(__half2*)&gc.x); acc.x += fmaf(v2, f.x, u2 * f.y);
        f = __half22float2(*(__half2*)&gc.y); acc.y += fmaf(v2, f.x, u2 * f.y);
        f = __half22float2(*(__half2*)&gc.z); acc.z += fmaf(v2, f.x, u2 * f.y);
        f = __half22float2(*(__half2*)&gc.w); acc.w += fmaf(v2, f.x, u2 * f.y);
        f = __half22float2(*(__half2*)&gd.x); acc.x += fmaf(v3, f.x, u3 * f.y);
        f = __half22float2(*(__half2*)&gd.y); acc.y += fmaf(v3, f.x, u3 * f.y);
        f = __half22float2(*(__half2*)&gd.z); acc.z += fmaf(v3, f.x, u3 * f.y);
        f = __half22float2(*(__half2*)&gd.w); acc.w += fmaf(v3, f.x, u3 * f.y);
    }
    for (; i < end; i++) {
        unsigned long long p = g_csr[i];
        uint4 ga = *(const uint4*)&g_h01h[(size_t)(unsigned)(p & 0xffffffffu) * 64 + c4];
        float u = __uint_as_float((unsigned)(p >> 32));
        float v = 1.f - u;
        float2 f;
        f = __half22float2(*(__half2*)&ga.x); acc.x += fmaf(v, f.x, u * f.y);
        f = __half22float2(*(__half2*)&ga.y); acc.y += fmaf(v, f.x, u * f.y);
        f = __half22float2(*(__half2*)&ga.z); acc.z += fmaf(v, f.x, u * f.y);
        f = __half22float2(*(__half2*)&ga.w); acc.w += fmaf(v, f.x, u * f.y);
    }

    float invd = 1.0f / fmaxf((float)(end - beg), 1.0f);
    float4 rr = *(const float4*)&g_r[(size_t)node * 64 + c4];
    float4 o;
    o.x = fmaf(acc.x, invd, rr.x);
    o.y = fmaf(acc.y, invd, rr.y);
    o.z = fmaf(acc.z, invd, rr.z);
    o.w = fmaf(acc.w, invd, rr.w);
    float* op = TO_GLOBAL ? g_h : out;
    *(float4*)&op[(size_t)node * 64 + c4] = o;
}

extern "C" void kernel_launch(void* const* d_in, const int* in_sizes, int n_in,
                              void* d_out, int out_size) {
    const float* x        = (const float*)d_in[0];
    const int* ei         = (const int*)d_in[1];
    const float* eattr    = (const float*)d_in[2];
    const float* w1       = (const float*)d_in[3];
    const float* root1    = (const float*)d_in[4];
    const float* b1       = (const float*)d_in[5];
    const float* w2       = (const float*)d_in[6];
    const float* root2    = (const float*)d_in[7];
    const float* b2       = (const float*)d_in[8];
    float* out            = (float*)d_out;

    const int GEMM_BLOCKS = (NN + 127) / 128;      // 782
    const int PULL_BLOCKS = NN / 16;               // 6250
    const int SCAN_BLOCKS = (NN + 1023) / 1024;    // 98

    // CSR build (edges shared by both layers)
    deg_zero_kernel<<<(NN + 255) / 256, 256>>>();
    deg_count_kernel<<<(NE + 255) / 256, 256>>>(ei);
    scan1_kernel<<<SCAN_BLOCKS, 1024>>>();
    scan23_kernel<<<(NN + 255) / 256, 256>>>();
    fill_kernel<<<(NE + 255) / 256, 256>>>(ei, eattr);

    // layer 1
    gemm3_tc_kernel<false><<<GEMM_BLOCKS, 256>>>(x, w1, root1, b1);
    pull_kernel<true><<<PULL_BLOCKS, 256>>>(out);

    // layer 2 (input = g_h)
    gemm3_tc_kernel<true><<<GEMM_BLOCKS, 256>>>(nullptr, w2, root2, b2);
    pull_kernel<false><<<PULL_BLOCKS, 256>>>(out);
}